// round 1
// baseline (speedup 1.0000x reference)
#include <cuda_runtime.h>

// Householder reflection per row:
//   out[b,:] = z[b,:] - 2 * v[b,:] * (v[b]·z[b]) / (v[b]·v[b])
// B = 8192 rows, L = 4096 cols, fp32.
//
// One CTA per row. 256 threads × 4 float4 = 4096 floats per row.
// Single pass: load v,z into registers, dual block-reduce (v·z, v·v),
// broadcast scale, write output from registers. 3 * 128 MiB HBM traffic.

constexpr int THREADS = 256;
constexpr int L4 = 4096 / 4;          // float4s per row
constexpr int PER_THREAD = L4 / THREADS;  // 4 float4 per thread

__global__ __launch_bounds__(THREADS, 8)
void householder_kernel(const float4* __restrict__ v,
                        const float4* __restrict__ z,
                        float4* __restrict__ out)
{
    const int row = blockIdx.x;
    const size_t base = (size_t)row * L4;
    const float4* vr = v + base;
    const float4* zr = z + base;
    float4* orow = out + base;

    float4 rv[PER_THREAD];
    float4 rz[PER_THREAD];

    float dvz = 0.0f;
    float dvv = 0.0f;

    // Front-batched loads: 8 independent LDG.128 in flight (MLP=8)
    #pragma unroll
    for (int i = 0; i < PER_THREAD; i++) {
        rv[i] = vr[threadIdx.x + i * THREADS];
    }
    #pragma unroll
    for (int i = 0; i < PER_THREAD; i++) {
        rz[i] = zr[threadIdx.x + i * THREADS];
    }

    #pragma unroll
    for (int i = 0; i < PER_THREAD; i++) {
        dvz += rv[i].x * rz[i].x + rv[i].y * rz[i].y
             + rv[i].z * rz[i].z + rv[i].w * rz[i].w;
        dvv += rv[i].x * rv[i].x + rv[i].y * rv[i].y
             + rv[i].z * rv[i].z + rv[i].w * rv[i].w;
    }

    // Warp reduce both dots
    #pragma unroll
    for (int off = 16; off > 0; off >>= 1) {
        dvz += __shfl_xor_sync(0xFFFFFFFFu, dvz, off);
        dvv += __shfl_xor_sync(0xFFFFFFFFu, dvv, off);
    }

    // Cross-warp reduce (8 warps)
    __shared__ float s_vz[8];
    __shared__ float s_vv[8];
    __shared__ float s_scale;

    const int lane = threadIdx.x & 31;
    const int wid  = threadIdx.x >> 5;
    if (lane == 0) {
        s_vz[wid] = dvz;
        s_vv[wid] = dvv;
    }
    __syncthreads();

    if (wid == 0) {
        float a = (lane < 8) ? s_vz[lane] : 0.0f;
        float b = (lane < 8) ? s_vv[lane] : 0.0f;
        #pragma unroll
        for (int off = 4; off > 0; off >>= 1) {
            a += __shfl_xor_sync(0xFFFFFFFFu, a, off);
            b += __shfl_xor_sync(0xFFFFFFFFu, b, off);
        }
        if (lane == 0) {
            s_scale = 2.0f * a / b;
        }
    }
    __syncthreads();

    const float scale = s_scale;

    #pragma unroll
    for (int i = 0; i < PER_THREAD; i++) {
        float4 o;
        o.x = rz[i].x - scale * rv[i].x;
        o.y = rz[i].y - scale * rv[i].y;
        o.z = rz[i].z - scale * rv[i].z;
        o.w = rz[i].w - scale * rv[i].w;
        orow[threadIdx.x + i * THREADS] = o;
    }
}

extern "C" void kernel_launch(void* const* d_in, const int* in_sizes, int n_in,
                              void* d_out, int out_size)
{
    const float4* v = (const float4*)d_in[0];
    const float4* z = (const float4*)d_in[1];
    float4* out = (float4*)d_out;

    const int B = in_sizes[0] / 4096;   // 8192
    householder_kernel<<<B, THREADS>>>(v, z, out);
}